// round 4
// baseline (speedup 1.0000x reference)
#include <cuda_runtime.h>

#define H_N      1500
#define G4       6000
#define T_STEPS  4096
#define MLP_HID_N 1875
#define OUT_N    20
#define IN_N     20
#define NCTA     148
#define NTHREADS 512
#define NB_ROWS  12          // plane-B rows (smem)
#define WPAD_B   1508        // padded B row stride (floats)
#define MAXROWS  44
#define NCHUNK   24          // max float4 column-chunks per warp (375 = 7*24 + 9*23)

// ---------------- device scratch ----------------
__device__ float    g_xp[(size_t)T_STEPS * G4];
__device__ float    g_hbuf[2][1504];
__device__ float    g_hid[MLP_HID_N];
__device__ unsigned g_count;   // arrival counter (monotonic per launch)
__device__ unsigned g_epoch;   // release epoch written by CTA 0

#define FMA2(acc, a, b) \
    asm("fma.rn.f32x2 %0, %1, %2, %0;" : "+l"(acc) : "l"(a), "l"(b))

__device__ __forceinline__ float sigmoid_f(float x) {
    return __fdividef(1.f, 1.f + __expf(-x));
}
__device__ __forceinline__ float tanh_f(float x) {
    return __fdividef(2.f, 1.f + __expf(-2.f * x)) - 1.f;
}

// ---------------- pre: init state + x_proj ----------------
__global__ void pre_kernel(const float* __restrict__ inp,
                           const float* __restrict__ W_ih,
                           const float* __restrict__ b_ih,
                           const float* __restrict__ b_hh) {
    __shared__ float Wsm[256 * 21];
    __shared__ float bsm[256];
    __shared__ float insm[128 * IN_N];
    int tid = threadIdx.x;
    int r0 = blockIdx.x * 256;
    int t0 = blockIdx.y * 128;

    if (blockIdx.x == 0 && blockIdx.y == 0) {
        for (int i = tid; i < 1504; i += 256) {
            g_hbuf[0][i] = 0.f;
            g_hbuf[1][i] = 0.f;
        }
        if (tid == 0) { g_count = 0u; g_epoch = 0u; }
    }

    for (int i = tid; i < 256 * IN_N; i += 256) {
        int rr = i / IN_N, k = i % IN_N;
        int row = r0 + rr;
        Wsm[rr * 21 + k] = (row < G4) ? W_ih[row * IN_N + k] : 0.f;
    }
    {
        int row = r0 + tid;
        bsm[tid] = (row < G4) ? (b_ih[row] + b_hh[row]) : 0.f;
    }
    for (int i = tid; i < 128 * IN_N; i += 256)
        insm[i] = inp[t0 * IN_N + i];
    __syncthreads();

    int row = r0 + tid;
    if (row < G4) {
        const float* wrow = &Wsm[tid * 21];
        float bias = bsm[tid];
        for (int tt = 0; tt < 128; tt++) {
            const float* ir = &insm[tt * IN_N];
            float acc = bias;
            #pragma unroll
            for (int k = 0; k < IN_N; k++) acc += ir[k] * wrow[k];
            g_xp[(size_t)(t0 + tt) * G4 + row] = acc;
        }
    }
}

// ---------------- grid barrier helpers ----------------
__device__ __forceinline__ void gb_arrive() {
    asm volatile("fence.acq_rel.gpu;" ::: "memory");
    asm volatile("red.release.gpu.global.add.u32 [%0], 1;"
                 :: "l"(&g_count) : "memory");
}
__device__ __forceinline__ void gb_wait_count(unsigned target) {
    unsigned v;
    do {
        asm volatile("ld.acquire.gpu.global.u32 %0, [%1];"
                     : "=r"(v) : "l"(&g_count) : "memory");
    } while (v < target);
}
__device__ __forceinline__ void gb_release_epoch(unsigned e) {
    asm volatile("st.release.gpu.global.u32 [%0], %1;"
                 :: "l"(&g_epoch), "r"(e) : "memory");
}
__device__ __forceinline__ void gb_wait_epoch(unsigned e) {
    unsigned v;
    do {
        asm volatile("ld.acquire.gpu.global.u32 %0, [%1];"
                     : "=r"(v) : "l"(&g_epoch) : "memory");
    } while (v < e);
}

// ---------------- persistent LSTM + MLP ----------------
__global__ void __launch_bounds__(NTHREADS, 1)
lstm_kernel(const float* __restrict__ W_hh,
            const float* __restrict__ W1,
            const float* __restrict__ b1,
            const float* __restrict__ W2,
            const float* __restrict__ b2,
            float* __restrict__ out) {
    extern __shared__ float smem[];
    float* Wb_s  = smem;                         // NB_ROWS * WPAD_B
    float* h_s   = Wb_s + NB_ROWS * WPAD_B;      // 1504
    float* part  = h_s + 1504;                   // MAXROWS * 17
    float* xp_s  = part + MAXROWS * 17;          // MAXROWS
    float* c_s   = xp_s + MAXROWS;               // 16

    const int tid  = threadIdx.x;
    const int lane = tid & 31;
    const int w    = tid >> 5;
    const int b    = blockIdx.x;
    const int nu   = (b < 20) ? 11 : 10;
    const int u0   = (b < 20) ? b * 11 : 220 + (b - 20) * 10;
    const int nrows = 4 * nu;
    const int nA    = nrows - NB_ROWS;           // 32 or 28 plane-A rows

    const int NK    = (w < 7) ? 24 : 23;
    const int start = (w < 7) ? w * 24 : 168 + (w - 7) * 23;

    // ---- preload plane-B weights into smem ----
    for (int idx = tid; idx < NB_ROWS * (WPAD_B / 4); idx += NTHREADS) {
        int r = idx / (WPAD_B / 4), c4 = idx % (WPAD_B / 4);
        float4 v = make_float4(0.f, 0.f, 0.f, 0.f);
        if (c4 < 375) {
            int lr = nA + r;
            int grow = (lr / nu) * H_N + u0 + (lr % nu);
            v = *(const float4*)&W_hh[(size_t)grow * H_N + c4 * 4];
        }
        *(float4*)&Wb_s[r * WPAD_B + c4 * 4] = v;
    }
    if (tid < nu) c_s[tid] = 0.f;

    // ---- preload plane-A weights into registers ----
    ulonglong2 wA[NCHUNK];
    {
        const float* wrowA = W_hh;
        bool haveA = (lane < nA);
        if (haveA) {
            int grow = (lane / nu) * H_N + u0 + (lane % nu);
            wrowA = &W_hh[(size_t)grow * H_N];
        }
        #pragma unroll
        for (int k = 0; k < NCHUNK; k++) {
            if (haveA && k < NK)
                wA[k] = *(const ulonglong2*)&wrowA[(start + k) * 4];
            else
                wA[k] = make_ulonglong2(0ull, 0ull);
        }
    }

    const float* wrowB = &Wb_s[(lane % NB_ROWS) * WPAD_B];

    int xrow = 0;
    if (tid < nrows) xrow = (tid / nu) * H_N + u0 + (tid % nu);

    // prefetch xp for t=0
    float xp_cur = 0.f;
    if (tid < nrows) xp_cur = __ldcs(&g_xp[xrow]);

    __syncthreads();

    for (int t = 0; t < T_STEPS; t++) {
        // prefetch xp for t+1 (independent of h; overlaps everything below)
        float xp_next = 0.f;
        if (tid < nrows && t + 1 < T_STEPS)
            xp_next = __ldcs(&g_xp[(size_t)(t + 1) * G4 + xrow]);

        // fetch h(t) via L2 and stage to smem
        const float* hb = g_hbuf[t & 1];
        if (tid < 376) {
            float4 hv4 = __ldcg((const float4*)&hb[tid * 4]);
            *(float4*)&h_s[tid * 4] = hv4;
        }
        __syncthreads();

        // ---- matvec: packed f32x2 FMAs (tail chunk zeroed on 23-chunk warps) ----
        unsigned long long aA0 = 0ull, aA1 = 0ull, aB0 = 0ull, aB1 = 0ull;
        const float* hbase = &h_s[start * 4];
        #pragma unroll
        for (int k = 0; k < NCHUNK; k++) {
            ulonglong2 hv = (k < NK) ? *(const ulonglong2*)&hbase[k * 4]
                                     : make_ulonglong2(0ull, 0ull);
            FMA2(aA0, wA[k].x, hv.x);
            FMA2(aA1, wA[k].y, hv.y);
            ulonglong2 wb = (k < NK) ? *(const ulonglong2*)&wrowB[(start + k) * 4]
                                     : make_ulonglong2(0ull, 0ull);
            FMA2(aB0, wb.x, hv.x);
            FMA2(aB1, wb.y, hv.y);
        }
        float accA, accB;
        {
            float2 a0 = *(float2*)&aA0, a1 = *(float2*)&aA1;
            accA = (a0.x + a0.y) + (a1.x + a1.y);
            float2 b0 = *(float2*)&aB0, b1 = *(float2*)&aB1;
            accB = (b0.x + b0.y) + (b1.x + b1.y);
        }
        if (lane < nA) part[lane * 17 + w] = accA;
        if (lane < NB_ROWS) part[(nA + lane) * 17 + w] = accB;
        if (tid < nrows) xp_s[tid] = xp_cur;
        __syncthreads();

        // ---- per-unit reduce + gates: warp u owns hidden unit u ----
        if (w < nu) {
            float g4v[4];
            #pragma unroll
            for (int gg = 0; gg < 4; gg++) {
                int row = gg * nu + w;
                float v = (lane < 16) ? part[row * 17 + lane] : 0.f;
                v += __shfl_xor_sync(0xffffffffu, v, 8);
                v += __shfl_xor_sync(0xffffffffu, v, 4);
                v += __shfl_xor_sync(0xffffffffu, v, 2);
                v += __shfl_xor_sync(0xffffffffu, v, 1);
                g4v[gg] = v + xp_s[row];
            }
            // activations in parallel on lanes 0-3
            int sel = lane & 3;
            float gv = g4v[sel];
            float act = (sel == 2) ? tanh_f(gv) : sigmoid_f(gv);
            float ig = __shfl_sync(0xffffffffu, act, 0);
            float fg = __shfl_sync(0xffffffffu, act, 1);
            float gg = __shfl_sync(0xffffffffu, act, 2);
            float og = __shfl_sync(0xffffffffu, act, 3);
            if (lane == 0) {
                float c = fg * c_s[w] + ig * gg;
                c_s[w] = c;
                g_hbuf[(t + 1) & 1][u0 + w] = og * tanh_f(c);
            }
        }
        xp_cur = xp_next;
        __syncthreads();

        // ---- two-phase epoch barrier ----
        if (tid == 0) {
            gb_arrive();
            if (b == 0) {
                gb_wait_count((unsigned)NCTA * (unsigned)(t + 1));
                gb_release_epoch((unsigned)(t + 1));
            } else {
                gb_wait_epoch((unsigned)(t + 1));
            }
        }
        __syncthreads();
    }

    // =================== MLP head (h final in g_hbuf[0]) ===================
    {
        int gw = b * 16 + w;
        if (gw < MLP_HID_N) {
            const float* wr = &W1[(size_t)gw * H_N];
            const float* hv = g_hbuf[0];
            float acc = 0.f;
            for (int c4 = lane; c4 < 375; c4 += 32) {
                float4 wv = *(const float4*)&wr[c4 * 4];
                float4 h4 = __ldcg((const float4*)&hv[c4 * 4]);
                acc += wv.x * h4.x + wv.y * h4.y + wv.z * h4.z + wv.w * h4.w;
            }
            acc += __shfl_xor_sync(0xffffffffu, acc, 16);
            acc += __shfl_xor_sync(0xffffffffu, acc, 8);
            acc += __shfl_xor_sync(0xffffffffu, acc, 4);
            acc += __shfl_xor_sync(0xffffffffu, acc, 2);
            acc += __shfl_xor_sync(0xffffffffu, acc, 1);
            if (lane == 0) g_hid[gw] = acc + b1[gw];
        }
        __syncthreads();
        if (tid == 0) gb_arrive();

        if (b == 0) {
            if (tid == 0)
                gb_wait_count((unsigned)NCTA * (unsigned)(T_STEPS + 1));
            __syncthreads();
            for (int r = w; r < OUT_N; r += 16) {
                const float* wr = &W2[(size_t)r * MLP_HID_N];
                float acc = 0.f;
                for (int c = lane; c < MLP_HID_N; c += 32)
                    acc += wr[c] * __ldcg(&g_hid[c]);
                acc += __shfl_xor_sync(0xffffffffu, acc, 16);
                acc += __shfl_xor_sync(0xffffffffu, acc, 8);
                acc += __shfl_xor_sync(0xffffffffu, acc, 4);
                acc += __shfl_xor_sync(0xffffffffu, acc, 2);
                acc += __shfl_xor_sync(0xffffffffu, acc, 1);
                if (lane == 0) out[r] = acc + b2[r];
            }
        }
    }
}

// ---------------- launch ----------------
extern "C" void kernel_launch(void* const* d_in, const int* in_sizes, int n_in,
                              void* d_out, int out_size) {
    const float* inp  = (const float*)d_in[0];
    const float* W_ih = (const float*)d_in[1];
    const float* W_hh = (const float*)d_in[2];
    const float* b_ih = (const float*)d_in[3];
    const float* b_hh = (const float*)d_in[4];
    const float* W1   = (const float*)d_in[5];
    const float* b1   = (const float*)d_in[6];
    const float* W2   = (const float*)d_in[7];
    const float* b2   = (const float*)d_in[8];
    float* out = (float*)d_out;

    size_t smem_bytes = (size_t)(NB_ROWS * WPAD_B + 1504 + MAXROWS * 17 + MAXROWS + 16)
                        * sizeof(float);
    cudaFuncSetAttribute(lstm_kernel, cudaFuncAttributeMaxDynamicSharedMemorySize,
                         (int)smem_bytes);

    pre_kernel<<<dim3(24, 32), 256>>>(inp, W_ih, b_ih, b_hh);
    lstm_kernel<<<NCTA, NTHREADS, smem_bytes>>>(W_hh, W1, b1, W2, b2, out);
}

// round 5
// speedup vs baseline: 1.0961x; 1.0961x over previous
#include <cuda_runtime.h>

#define H_N      1500
#define G4       6000
#define T_STEPS  4096
#define MLP_HID_N 1875
#define OUT_N    20
#define IN_N     20
#define NCTA     148
#define NTHREADS 512
#define NREP     8           // h replication factor (L2 de-hotspot)
#define NB_ROWS  12          // plane-B rows (smem)
#define WPAD_B   1508        // padded B row stride (floats)
#define MAXROWS  44
#define NCHUNK   24          // max float4 column-chunks per warp (375 = 7*24 + 9*23)

// ---------------- device scratch ----------------
__device__ float    g_xp[(size_t)T_STEPS * G4];
__device__ float    g_hrep[2][NREP][1504];     // double-buffered, 8-way replicated h
__device__ float    g_hid[MLP_HID_N];
__device__ unsigned g_count;                   // arrival counter (monotonic per launch)

#define FMA2(acc, a, b) \
    asm("fma.rn.f32x2 %0, %1, %2, %0;" : "+l"(acc) : "l"(a), "l"(b))

__device__ __forceinline__ float sigmoid_f(float x) {
    return __fdividef(1.f, 1.f + __expf(-x));
}
__device__ __forceinline__ float tanh_f(float x) {
    return __fdividef(2.f, 1.f + __expf(-2.f * x)) - 1.f;
}

// ---------------- pre: init state + x_proj ----------------
__global__ void pre_kernel(const float* __restrict__ inp,
                           const float* __restrict__ W_ih,
                           const float* __restrict__ b_ih,
                           const float* __restrict__ b_hh) {
    __shared__ float Wsm[256 * 21];
    __shared__ float bsm[256];
    __shared__ float insm[128 * IN_N];
    int tid = threadIdx.x;
    int r0 = blockIdx.x * 256;
    int t0 = blockIdx.y * 128;

    if (blockIdx.x == 0 && blockIdx.y == 0) {
        float* hz = &g_hrep[0][0][0];
        for (int i = tid; i < 2 * NREP * 1504; i += 256) hz[i] = 0.f;
        if (tid == 0) g_count = 0u;
    }

    for (int i = tid; i < 256 * IN_N; i += 256) {
        int rr = i / IN_N, k = i % IN_N;
        int row = r0 + rr;
        Wsm[rr * 21 + k] = (row < G4) ? W_ih[row * IN_N + k] : 0.f;
    }
    {
        int row = r0 + tid;
        bsm[tid] = (row < G4) ? (b_ih[row] + b_hh[row]) : 0.f;
    }
    for (int i = tid; i < 128 * IN_N; i += 256)
        insm[i] = inp[t0 * IN_N + i];
    __syncthreads();

    int row = r0 + tid;
    if (row < G4) {
        const float* wrow = &Wsm[tid * 21];
        float bias = bsm[tid];
        for (int tt = 0; tt < 128; tt++) {
            const float* ir = &insm[tt * IN_N];
            float acc = bias;
            #pragma unroll
            for (int k = 0; k < IN_N; k++) acc += ir[k] * wrow[k];
            g_xp[(size_t)(t0 + tt) * G4 + row] = acc;
        }
    }
}

// ---------------- grid barrier helpers ----------------
__device__ __forceinline__ void gb_arrive() {
    // release-add: orders all prior CTA writes (after bar.sync) before the count bump
    asm volatile("red.release.gpu.global.add.u32 [%0], 1;"
                 :: "l"(&g_count) : "memory");
}
__device__ __forceinline__ void gb_wait_count(unsigned target) {
    unsigned v;
    do {
        asm volatile("ld.relaxed.gpu.global.u32 %0, [%1];"
                     : "=r"(v) : "l"(&g_count) : "memory");
    } while (v < target);
    asm volatile("fence.acq_rel.gpu;" ::: "memory");
}

// ---------------- persistent LSTM + MLP ----------------
__global__ void __launch_bounds__(NTHREADS, 1)
lstm_kernel(const float* __restrict__ W_hh,
            const float* __restrict__ W1,
            const float* __restrict__ b1,
            const float* __restrict__ W2,
            const float* __restrict__ b2,
            float* __restrict__ out) {
    extern __shared__ float smem[];
    float* Wb_s  = smem;                         // NB_ROWS * WPAD_B
    float* h_s   = Wb_s + NB_ROWS * WPAD_B;      // 1504
    float* part  = h_s + 1504;                   // MAXROWS * 17
    float* xp_s  = part + MAXROWS * 17;          // MAXROWS
    float* c_s   = xp_s + MAXROWS;               // 16

    const int tid  = threadIdx.x;
    const int lane = tid & 31;
    const int w    = tid >> 5;
    const int b    = blockIdx.x;
    const int nu   = (b < 20) ? 11 : 10;
    const int u0   = (b < 20) ? b * 11 : 220 + (b - 20) * 10;
    const int nrows = 4 * nu;
    const int nA    = nrows - NB_ROWS;           // 32 or 28 plane-A rows

    const int NK    = (w < 7) ? 24 : 23;
    const int start = (w < 7) ? w * 24 : 168 + (w - 7) * 23;

    // ---- preload plane-B weights into smem ----
    for (int idx = tid; idx < NB_ROWS * (WPAD_B / 4); idx += NTHREADS) {
        int r = idx / (WPAD_B / 4), c4 = idx % (WPAD_B / 4);
        float4 v = make_float4(0.f, 0.f, 0.f, 0.f);
        if (c4 < 375) {
            int lr = nA + r;
            int grow = (lr / nu) * H_N + u0 + (lr % nu);
            v = *(const float4*)&W_hh[(size_t)grow * H_N + c4 * 4];
        }
        *(float4*)&Wb_s[r * WPAD_B + c4 * 4] = v;
    }
    if (tid < nu) c_s[tid] = 0.f;

    // ---- preload plane-A weights into registers ----
    ulonglong2 wA[NCHUNK];
    {
        const float* wrowA = W_hh;
        bool haveA = (lane < nA);
        if (haveA) {
            int grow = (lane / nu) * H_N + u0 + (lane % nu);
            wrowA = &W_hh[(size_t)grow * H_N];
        }
        #pragma unroll
        for (int k = 0; k < NCHUNK; k++) {
            if (haveA && k < NK)
                wA[k] = *(const ulonglong2*)&wrowA[(start + k) * 4];
            else
                wA[k] = make_ulonglong2(0ull, 0ull);
        }
    }

    const float* wrowB = &Wb_s[(lane % NB_ROWS) * WPAD_B];

    int xrow = 0;
    if (tid < nrows) xrow = (tid / nu) * H_N + u0 + (tid % nu);

    // prefetch xp for t=0
    float xp_cur = 0.f;
    if (tid < nrows) xp_cur = __ldcs(&g_xp[xrow]);

    __syncthreads();

    for (int t = 0; t < T_STEPS; t++) {
        // prefetch xp for t+1 (independent of h; overlaps everything below)
        float xp_next = 0.f;
        if (tid < nrows && t + 1 < T_STEPS)
            xp_next = __ldcs(&g_xp[(size_t)(t + 1) * G4 + xrow]);

        // fetch h(t) from this CTA's replica and stage to smem
        const float* hb = g_hrep[t & 1][b & (NREP - 1)];
        if (tid < 376) {
            float4 hv4 = __ldcg((const float4*)&hb[tid * 4]);
            *(float4*)&h_s[tid * 4] = hv4;
        }
        __syncthreads();

        // ---- matvec: packed f32x2 FMAs (tail chunk zeroed on 23-chunk warps) ----
        unsigned long long aA0 = 0ull, aA1 = 0ull, aB0 = 0ull, aB1 = 0ull;
        const float* hbase = &h_s[start * 4];
        #pragma unroll
        for (int k = 0; k < NCHUNK; k++) {
            ulonglong2 hv = (k < NK) ? *(const ulonglong2*)&hbase[k * 4]
                                     : make_ulonglong2(0ull, 0ull);
            FMA2(aA0, wA[k].x, hv.x);
            FMA2(aA1, wA[k].y, hv.y);
            ulonglong2 wb = (k < NK) ? *(const ulonglong2*)&wrowB[(start + k) * 4]
                                     : make_ulonglong2(0ull, 0ull);
            FMA2(aB0, wb.x, hv.x);
            FMA2(aB1, wb.y, hv.y);
        }
        float accA, accB;
        {
            float2 a0 = *(float2*)&aA0, a1 = *(float2*)&aA1;
            accA = (a0.x + a0.y) + (a1.x + a1.y);
            float2 b0 = *(float2*)&aB0, b1 = *(float2*)&aB1;
            accB = (b0.x + b0.y) + (b1.x + b1.y);
        }
        if (lane < nA) part[lane * 17 + w] = accA;
        if (lane < NB_ROWS) part[(nA + lane) * 17 + w] = accB;
        if (tid < nrows) xp_s[tid] = xp_cur;
        __syncthreads();

        // ---- per-unit reduce + gates: warp u owns hidden unit u ----
        if (w < nu) {
            float g4v[4];
            #pragma unroll
            for (int gg = 0; gg < 4; gg++) {
                int row = gg * nu + w;
                float v = (lane < 16) ? part[row * 17 + lane] : 0.f;
                v += __shfl_xor_sync(0xffffffffu, v, 8);
                v += __shfl_xor_sync(0xffffffffu, v, 4);
                v += __shfl_xor_sync(0xffffffffu, v, 2);
                v += __shfl_xor_sync(0xffffffffu, v, 1);
                g4v[gg] = v + xp_s[row];
            }
            // activations in parallel on lanes 0-3
            int sel = lane & 3;
            float gv = g4v[sel];
            float act = (sel == 2) ? tanh_f(gv) : sigmoid_f(gv);
            float ig = __shfl_sync(0xffffffffu, act, 0);
            float fg = __shfl_sync(0xffffffffu, act, 1);
            float gg = __shfl_sync(0xffffffffu, act, 2);
            float og = __shfl_sync(0xffffffffu, act, 3);
            float hval = 0.f;
            if (lane == 0) {
                float c = fg * c_s[w] + ig * gg;
                c_s[w] = c;
                hval = og * tanh_f(c);
            }
            hval = __shfl_sync(0xffffffffu, hval, 0);
            // write h to all NREP replicas (lanes 0-7, one replica each)
            if (lane < NREP)
                g_hrep[(t + 1) & 1][lane][u0 + w] = hval;
        }
        xp_cur = xp_next;
        __syncthreads();

        // ---- grid barrier: release-add, relaxed all-poll ----
        if (tid == 0) {
            gb_arrive();
            gb_wait_count((unsigned)NCTA * (unsigned)(t + 1));
        }
        __syncthreads();
    }

    // =================== MLP head (h final in g_hrep[0][*]) ===================
    {
        int gw = b * 16 + w;
        if (gw < MLP_HID_N) {
            const float* wr = &W1[(size_t)gw * H_N];
            const float* hv = g_hrep[0][b & (NREP - 1)];
            float acc = 0.f;
            for (int c4 = lane; c4 < 375; c4 += 32) {
                float4 wv = *(const float4*)&wr[c4 * 4];
                float4 h4 = __ldcg((const float4*)&hv[c4 * 4]);
                acc += wv.x * h4.x + wv.y * h4.y + wv.z * h4.z + wv.w * h4.w;
            }
            acc += __shfl_xor_sync(0xffffffffu, acc, 16);
            acc += __shfl_xor_sync(0xffffffffu, acc, 8);
            acc += __shfl_xor_sync(0xffffffffu, acc, 4);
            acc += __shfl_xor_sync(0xffffffffu, acc, 2);
            acc += __shfl_xor_sync(0xffffffffu, acc, 1);
            if (lane == 0) g_hid[gw] = acc + b1[gw];
        }
        __syncthreads();
        if (tid == 0) gb_arrive();

        if (b == 0) {
            if (tid == 0)
                gb_wait_count((unsigned)NCTA * (unsigned)(T_STEPS + 1));
            __syncthreads();
            for (int r = w; r < OUT_N; r += 16) {
                const float* wr = &W2[(size_t)r * MLP_HID_N];
                float acc = 0.f;
                for (int c = lane; c < MLP_HID_N; c += 32)
                    acc += wr[c] * __ldcg(&g_hid[c]);
                acc += __shfl_xor_sync(0xffffffffu, acc, 16);
                acc += __shfl_xor_sync(0xffffffffu, acc, 8);
                acc += __shfl_xor_sync(0xffffffffu, acc, 4);
                acc += __shfl_xor_sync(0xffffffffu, acc, 2);
                acc += __shfl_xor_sync(0xffffffffu, acc, 1);
                if (lane == 0) out[r] = acc + b2[r];
            }
        }
    }
}

// ---------------- launch ----------------
extern "C" void kernel_launch(void* const* d_in, const int* in_sizes, int n_in,
                              void* d_out, int out_size) {
    const float* inp  = (const float*)d_in[0];
    const float* W_ih = (const float*)d_in[1];
    const float* W_hh = (const float*)d_in[2];
    const float* b_ih = (const float*)d_in[3];
    const float* b_hh = (const float*)d_in[4];
    const float* W1   = (const float*)d_in[5];
    const float* b1   = (const float*)d_in[6];
    const float* W2   = (const float*)d_in[7];
    const float* b2   = (const float*)d_in[8];
    float* out = (float*)d_out;

    size_t smem_bytes = (size_t)(NB_ROWS * WPAD_B + 1504 + MAXROWS * 17 + MAXROWS + 16)
                        * sizeof(float);
    cudaFuncSetAttribute(lstm_kernel, cudaFuncAttributeMaxDynamicSharedMemorySize,
                         (int)smem_bytes);

    pre_kernel<<<dim3(24, 32), 256>>>(inp, W_ih, b_ih, b_hh);
    lstm_kernel<<<NCTA, NTHREADS, smem_bytes>>>(W_hh, W1, b1, W2, b2, out);
}